// round 15
// baseline (speedup 1.0000x reference)
#include <cuda_runtime.h>
#include <cuda_fp16.h>
#include <math.h>
#include <stdint.h>

// Problem constants
#define Bb 4
#define Ss 2048
#define Dd 1024
#define Mm 4

// Compact row layout: per modality m, rows [moff[m], moff[m]+4*sl[m])
// sl = {2048,1024,1500,512}; moff = {0, 8192, 12288, 18288}; total 20336 rows.
#define RTOT 20336

// ---------------------------------------------------------------------------
// Device-global scratch (allocation-free rule)
__device__ __align__(16) __half g_xs1[17825792];   // x inputs, fp16 hi only
__device__ __align__(16) __half g_ws1[8650752];    // weights hi
__device__ __align__(16) __half g_ws2[8650752];    // weights lo (QKV/O region only)
__device__ __align__(16) __half g_sb1[20824064];   // compact stacked, fp16 hi
__device__ __align__(16) __half g_Qh[20824064];    // compact Q, fp16
__device__ __align__(16) __half g_Kh[20824064];    // compact K, fp16
__device__ __align__(16) __half g_Vh[20824064];    // compact V, fp16
__device__ __align__(16) __half g_fb1[8388608];    // fused (B,S,D), fp16 hi

// ---------------------------------------------------------------------------
// Batched fp32 -> fp16 convert/split: 12 jobs in one launch, 4 float4/thread.
struct ConvJobs {
    const float4* src[12];
    __half2*      d1[12];
    __half2*      d2[12];    // nullptr -> hi-only convert
    int           start[13]; // block-index prefix (1024 float4 per block)
};

__global__ __launch_bounds__(256)
void conv_all(ConvJobs jobs) {
    int blk = blockIdx.x;
    int j = 0;
    #pragma unroll
    for (int i = 1; i < 12; ++i)
        if (blk >= jobs.start[i]) j = i;
    int base = (blk - jobs.start[j]) * 1024 + threadIdx.x;

    const float4* src = jobs.src[j];
    float4 v[4];
    #pragma unroll
    for (int u = 0; u < 4; ++u) v[u] = src[base + 256 * u];

    __half2* d1 = jobs.d1[j];
    __half2* d2 = jobs.d2[j];
    #pragma unroll
    for (int u = 0; u < 4; ++u) {
        int i4 = base + 256 * u;
        __half h0 = __float2half_rn(v[u].x);
        __half h1 = __float2half_rn(v[u].y);
        __half h2 = __float2half_rn(v[u].z);
        __half h3 = __float2half_rn(v[u].w);
        d1[2*i4]   = __halves2half2(h0, h1);
        d1[2*i4+1] = __halves2half2(h2, h3);
        if (d2) {
            __half l0 = __float2half_rn(v[u].x - __half2float(h0));
            __half l1 = __float2half_rn(v[u].y - __half2float(h1));
            __half l2 = __float2half_rn(v[u].z - __half2float(h2));
            __half l3 = __float2half_rn(v[u].w - __half2float(h3));
            d2[2*i4]   = __halves2half2(l0, l1);
            d2[2*i4+1] = __halves2half2(l2, l3);
        }
    }
}

// ---------------------------------------------------------------------------
// fp16 split GEMM body, BM=128 x BN=256, BK=32, 512 threads (16 warps 2Mx8N,
// per-warp tile 64x32 — identical per-warp math/order to the previous 256-thr
// version, so results are bit-identical). Terms: Ah*Wh (+ Ah*Wl if W2).
// Halved L2 staging traffic per MMA vs BN=128 (A loaded once per 256 cols).

#define ROWB 80                       // smem row stride bytes (conflict-free)
#define ARRB_A (128 * ROWB)           // 10240 B (A: 128 rows)
#define ARRB_W (256 * ROWB)           // 20480 B (W: 256 rows)
#define STAGE1 (ARRB_A + ARRB_W)            // 30720 B (1-term)
#define STAGE2 (ARRB_A + 2 * ARRB_W)        // 51200 B (2-term)
#define NSTAGE 3

__device__ __forceinline__ void mma_fp16(float* c, const unsigned* a, const unsigned* b) {
    asm volatile(
        "mma.sync.aligned.m16n8k16.row.col.f32.f16.f16.f32 "
        "{%0,%1,%2,%3}, {%4,%5,%6,%7}, {%8,%9}, {%0,%1,%2,%3};\n"
        : "+f"(c[0]), "+f"(c[1]), "+f"(c[2]), "+f"(c[3])
        : "r"(a[0]), "r"(a[1]), "r"(a[2]), "r"(a[3]), "r"(b[0]), "r"(b[1]));
}

__device__ __forceinline__ void ldsm4(unsigned& r0, unsigned& r1, unsigned& r2, unsigned& r3,
                                      unsigned addr) {
    asm volatile("ldmatrix.sync.aligned.m8n8.x4.shared.b16 {%0,%1,%2,%3}, [%4];"
                 : "=r"(r0), "=r"(r1), "=r"(r2), "=r"(r3) : "r"(addr));
}

__device__ __forceinline__ void cp16(unsigned dst, const void* src, bool valid) {
    int sz = valid ? 16 : 0;
    asm volatile("cp.async.cg.shared.global [%0], [%1], 16, %2;\n"
                 :: "r"(dst), "l"(src), "r"(sz));
}

__device__ __forceinline__
void gemm_body(const __half* __restrict__ A1,
               const __half* __restrict__ W1, const __half* __restrict__ W2,
               const float* __restrict__ bias, const float* __restrict__ extra,
               float* __restrict__ outF, __half* __restrict__ o1,
               int R, int Kd, int row0, int wcol0, int ocol0, int stageB)
{
    extern __shared__ __align__(16) char smem[];
    const unsigned smem32 = (unsigned)__cvta_generic_to_shared(smem);

    const int tid  = threadIdx.x;    // 0..511
    const int warp = tid >> 5;       // 0..15
    const int lane = tid & 31;
    const int wm = (warp >> 3) * 64; // 2 warps in M
    const int wn = (warp & 7) * 32;  // 8 warps in N

    // loader mapping: A = 512 16B-chunks (1/thread); W = 1024 chunks (2/thread)
    const int arow = tid >> 2, acol = tid & 3;
    const int w0r = tid >> 2,         w0k = tid & 3;
    const int w1r = (tid + 512) >> 2, w1k = tid & 3;

    // ldmatrix per-lane offsets (identical to previous version)
    const int lane7 = lane & 7;
    const int j     = lane >> 3;
    const int aRow  = (j & 1) * 8 + lane7;
    const int aKb   = (j >> 1) * 16;
    const int bRow  = (j >> 1) * 8 + lane7;
    const int bKb   = (j & 1) * 16;

    float acc[4][4][4];
    #pragma unroll
    for (int i = 0; i < 4; ++i)
        #pragma unroll
        for (int k = 0; k < 4; ++k)
            #pragma unroll
            for (int l = 0; l < 4; ++l) acc[i][k][l] = 0.f;

    const int nT = Kd >> 5;   // BK = 32

    auto load_tile = [&](int t) {
        unsigned sb = smem32 + (t % NSTAGE) * stageB;
        int kt = t << 5;
        {
            bool v0 = (row0 + arow) < R;
            size_t sr = v0 ? (size_t)(row0 + arow) : 0;
            cp16(sb + arow*ROWB + acol*16, A1 + sr*Kd + kt + acol*8, v0);
        }
        {
            size_t sr0 = (size_t)(wcol0 + w0r);
            size_t sr1 = (size_t)(wcol0 + w1r);
            cp16(sb + ARRB_A + w0r*ROWB + w0k*16, W1 + sr0*Kd + kt + w0k*8, true);
            cp16(sb + ARRB_A + w1r*ROWB + w1k*16, W1 + sr1*Kd + kt + w1k*8, true);
            if (W2) {
                cp16(sb + ARRB_A + ARRB_W + w0r*ROWB + w0k*16, W2 + sr0*Kd + kt + w0k*8, true);
                cp16(sb + ARRB_A + ARRB_W + w1r*ROWB + w1k*16, W2 + sr1*Kd + kt + w1k*8, true);
            }
        }
    };

    load_tile(0);
    asm volatile("cp.async.commit_group;" ::: "memory");
    if (nT > 1) {
        load_tile(1);
        asm volatile("cp.async.commit_group;" ::: "memory");
    }

    for (int t = 0; t < nT; ++t) {
        if (t + 1 < nT) asm volatile("cp.async.wait_group 1;" ::: "memory");
        else            asm volatile("cp.async.wait_group 0;" ::: "memory");
        __syncthreads();
        if (t + 2 < nT) {
            load_tile(t + 2);
            asm volatile("cp.async.commit_group;" ::: "memory");
        }
        const unsigned s0 = smem32 + (t % NSTAGE) * stageB;

        #pragma unroll
        for (int ks = 0; ks < 2; ++ks) {
            const int kb = ks * 32;
            unsigned a[4][4], bH[4][2], bL[4][2];
            #pragma unroll
            for (int mt = 0; mt < 4; ++mt)
                ldsm4(a[mt][0], a[mt][1], a[mt][2], a[mt][3],
                      s0 + (unsigned)(wm + mt*16 + aRow) * ROWB + kb + aKb);
            #pragma unroll
            for (int np = 0; np < 2; ++np) {
                unsigned r0, r1, r2, r3;
                ldsm4(r0, r1, r2, r3,
                      s0 + ARRB_A + (unsigned)(wn + np*16 + bRow) * ROWB + kb + bKb);
                bH[np*2][0] = r0; bH[np*2][1] = r1; bH[np*2+1][0] = r2; bH[np*2+1][1] = r3;
            }
            if (W2) {
                #pragma unroll
                for (int np = 0; np < 2; ++np) {
                    unsigned r0, r1, r2, r3;
                    ldsm4(r0, r1, r2, r3,
                          s0 + ARRB_A + ARRB_W + (unsigned)(wn + np*16 + bRow) * ROWB + kb + bKb);
                    bL[np*2][0] = r0; bL[np*2][1] = r1; bL[np*2+1][0] = r2; bL[np*2+1][1] = r3;
                }
            }
            #pragma unroll
            for (int mt = 0; mt < 4; ++mt)
                #pragma unroll
                for (int nt = 0; nt < 4; ++nt)
                    mma_fp16(acc[mt][nt], a[mt], bH[nt]);
            if (W2) {
                #pragma unroll
                for (int mt = 0; mt < 4; ++mt)
                    #pragma unroll
                    for (int nt = 0; nt < 4; ++nt)
                        mma_fp16(acc[mt][nt], a[mt], bL[nt]);
            }
        }
    }

    // ---- epilogue (contiguous rows; hi-only fp16 or fp32)
    const int tg = lane >> 2;
    const int tc = 2 * (lane & 3);
    #pragma unroll
    for (int mt = 0; mt < 4; ++mt) {
        #pragma unroll
        for (int half_ = 0; half_ < 2; ++half_) {
            int r = row0 + wm + mt*16 + tg + half_*8;
            if (r >= R) continue;
            long rowIdx = (long)r * 1024;
            #pragma unroll
            for (int nt = 0; nt < 4; ++nt) {
                int c = ocol0 + wn + nt*8 + tc;
                float v0 = acc[mt][nt][half_*2 + 0] + bias[c];
                float v1 = acc[mt][nt][half_*2 + 1] + bias[c + 1];
                if (extra) { v0 += extra[c]; v1 += extra[c + 1]; }
                if (outF) {
                    *(float2*)(outF + rowIdx + c) = make_float2(v0, v1);
                } else {
                    *(__half2*)(o1 + rowIdx + c) =
                        __halves2half2(__float2half_rn(v0), __float2half_rn(v1));
                }
            }
        }
    }
}

// ---------------------------------------------------------------------------
// Output projection -> fp32 d_out, 2-term. grid (4, R/128).
__global__ __launch_bounds__(512, 1)
void gemm_one(const __half* __restrict__ A1,
              const __half* __restrict__ W1, const __half* __restrict__ W2,
              const float* __restrict__ bias, float* __restrict__ outF,
              int R, int Kd)
{
    int col0 = blockIdx.x * 256;
    gemm_body(A1, W1, W2, bias, nullptr, outF, nullptr,
              R, Kd, blockIdx.y * 128, col0, col0, STAGE2);
}

// Q+K projection, 1-TERM, homogeneous. grid (8, 159). Tiles 0-3 = Q, 4-7 = K.
__global__ __launch_bounds__(512, 1)
void gemm_qk(const __half* __restrict__ A1, const __half* __restrict__ W1,
             const float* __restrict__ b0, const float* __restrict__ b1,
             __half* __restrict__ Qh, __half* __restrict__ Kh, int R)
{
    int wcol0 = blockIdx.x * 256;           // 0..1792
    int cblk  = wcol0 >> 10;                // 0=Q 1=K (uniform per CTA)
    int row0  = blockIdx.y * 128;
    int ocol0 = wcol0 & 1023;
    const float* bias = (cblk == 0) ? b0 : b1;
    __half* out       = (cblk == 0) ? Qh : Kh;
    gemm_body(A1, W1, nullptr, bias, nullptr, nullptr, out,
              R, 1024, row0, wcol0, ocol0, STAGE1);
}

// V projection, 2-term, fp16 store. grid (4, 159).
__global__ __launch_bounds__(512, 1)
void gemm_v(const __half* __restrict__ A1,
            const __half* __restrict__ W1, const __half* __restrict__ W2,
            const float* __restrict__ bias, __half* __restrict__ Vh, int R)
{
    int wcol0 = 2048 + blockIdx.x * 256;    // V rows of W arena
    gemm_body(A1, W1, W2, bias, nullptr, nullptr, Vh,
              R, 1024, blockIdx.y * 128, wcol0, wcol0 & 1023, STAGE2);
}

// Merged modality projections: 4 jobs, grid (4, 159), 1-TERM.
struct GemmJob {
    const __half *A1, *W1;
    const float *bias, *extra;
    __half *o1;
    int R, Kd, blkStart;
};
struct Jobs4 { GemmJob j[4]; };

__global__ __launch_bounds__(512, 1)
void gemm_proj(Jobs4 jobs)
{
    int by = blockIdx.y;
    GemmJob jb = jobs.j[0];
    if (by >= jobs.j[1].blkStart) jb = jobs.j[1];
    if (by >= jobs.j[2].blkStart) jb = jobs.j[2];
    if (by >= jobs.j[3].blkStart) jb = jobs.j[3];
    int row0 = (by - jb.blkStart) * 128;
    int col0 = blockIdx.x * 256;
    gemm_body(jb.A1, jb.W1, nullptr, jb.bias, jb.extra, nullptr, jb.o1,
              jb.R, jb.Kd, row0, col0, col0, STAGE1);
}

// ---------------------------------------------------------------------------
// Routed per-position attention + modality mean over COMPACT Q/K/V (all fp16).
// ROUTES (compile-time, replicates reference float64 Cantor math incl. ties):
//   [[0,1,2],[0,1,2],[2,3,0],[3,2,0]]
// Padded positions (s >= sl[m]) substitute zeros.
// 256 threads/block: warp handles 2 heads (16 lanes each, half4 lanes).
__global__ __launch_bounds__(256)
void attn_kernel(const __half* __restrict__ Q, const __half* __restrict__ K,
                 const __half* __restrict__ V, const float* __restrict__ tptr,
                 __half* __restrict__ f1)
{
    const int routes[4][3] = {{0,1,2},{0,1,2},{2,3,0},{3,2,0}};
    const int sls[4]  = {2048, 1024, 1500, 512};
    const int moff[4] = {0, 8192, 12288, 18288};

    int bs   = blockIdx.x;
    int b    = bs >> 11;
    int s    = bs & (Ss - 1);
    int warp = threadIdx.x >> 5;      // 0..7 -> heads 2w, 2w+1
    int lane = threadIdx.x & 31;
    int sub  = lane >> 4;             // which head of the pair
    int l16  = lane & 15;
    int h    = warp * 2 + sub;

    const float scale = 1.0f / (8.0f * fabsf(*tptr));
    const int lo = h * 64 + l16 * 4;  // element offset of this lane's 4 elems

    long off[4];
    bool valid[4];
    #pragma unroll
    for (int m = 0; m < 4; ++m) {
        valid[m] = (s < sls[m]);
        off[m] = valid[m] ? (((long)moff[m] + (long)b * sls[m] + s) * Dd + lo) : 0;
    }

    // Load each distinct Q/K/V vector exactly once (half4 -> float4)
    float4 q[4], k[4], v[4];
    #pragma unroll
    for (int m = 0; m < 4; ++m) {
        if (valid[m]) {
            __half2 a0 = *(const __half2*)(Q + off[m]);
            __half2 a1 = *(const __half2*)(Q + off[m] + 2);
            float2 fa = __half22float2(a0), fb = __half22float2(a1);
            q[m] = make_float4(fa.x, fa.y, fb.x, fb.y);
            a0 = *(const __half2*)(K + off[m]);
            a1 = *(const __half2*)(K + off[m] + 2);
            fa = __half22float2(a0); fb = __half22float2(a1);
            k[m] = make_float4(fa.x, fa.y, fb.x, fb.y);
            a0 = *(const __half2*)(V + off[m]);
            a1 = *(const __half2*)(V + off[m] + 2);
            fa = __half22float2(a0); fb = __half22float2(a1);
            v[m] = make_float4(fa.x, fa.y, fb.x, fb.y);
        } else {
            q[m] = make_float4(0.f, 0.f, 0.f, 0.f);
            k[m] = q[m];
            v[m] = q[m];
        }
    }

    // 12 partial dots, then butterfly-reduce within each 16-lane head group
    float d[4][3];
    #pragma unroll
    for (int m = 0; m < 4; ++m)
        #pragma unroll
        for (int jj = 0; jj < 3; ++jj) {
            const float4 kk = k[routes[m][jj]];
            d[m][jj] = q[m].x*kk.x + q[m].y*kk.y + q[m].z*kk.z + q[m].w*kk.w;
        }
    #pragma unroll
    for (int offs = 8; offs > 0; offs >>= 1)
        #pragma unroll
        for (int m = 0; m < 4; ++m)
            #pragma unroll
            for (int jj = 0; jj < 3; ++jj)
                d[m][jj] += __shfl_xor_sync(0xffffffffu, d[m][jj], offs);

    // Softmax per m + weighted V accumulation
    float4 acc = make_float4(0.f, 0.f, 0.f, 0.f);
    #pragma unroll
    for (int m = 0; m < 4; ++m) {
        float sc0 = d[m][0] * scale;
        float sc1 = d[m][1] * scale;
        float sc2 = d[m][2] * scale;
        float mx = fmaxf(sc0, fmaxf(sc1, sc2));
        float e0 = expf(sc0 - mx);
        float e1 = expf(sc1 - mx);
        float e2 = expf(sc2 - mx);
        float inv = 1.0f / (e0 + e1 + e2);
        float a0 = e0 * inv, a1 = e1 * inv, a2 = e2 * inv;
        const float4 v0 = v[routes[m][0]];
        const float4 v1 = v[routes[m][1]];
        const float4 v2 = v[routes[m][2]];
        acc.x += a0 * v0.x + a1 * v1.x + a2 * v2.x;
        acc.y += a0 * v0.y + a1 * v1.y + a2 * v2.y;
        acc.z += a0 * v0.z + a1 * v1.z + a2 * v2.z;
        acc.w += a0 * v0.w + a1 * v1.w + a2 * v2.w;
    }

    long o = ((long)b * Ss + s) * Dd + lo;
    __half2 p0 = __floats2half2_rn(acc.x * 0.25f, acc.y * 0.25f);
    __half2 p1 = __floats2half2_rn(acc.z * 0.25f, acc.w * 0.25f);
    uint2 pk;
    pk.x = *(unsigned*)&p0;
    pk.y = *(unsigned*)&p1;
    *(uint2*)(f1 + o) = pk;
}

// ---------------------------------------------------------------------------
extern "C" void kernel_launch(void* const* d_in, const int* in_sizes, int n_in,
                              void* d_out, int out_size)
{
    const float *x[4], *Wm[4], *bm[4];
    const float *mod_emb, *Wq, *bq, *Wk, *bk, *Wv, *bv, *Wo, *bo, *temp;

    if (in_sizes[1] == 786432) {
        x[0]  = (const float*)d_in[0];  Wm[0] = (const float*)d_in[1];  bm[0] = (const float*)d_in[2];
        x[1]  = (const float*)d_in[3];  Wm[1] = (const float*)d_in[4];  bm[1] = (const float*)d_in[5];
        x[2]  = (const float*)d_in[6];  Wm[2] = (const float*)d_in[7];  bm[2] = (const float*)d_in[8];
        x[3]  = (const float*)d_in[9];  Wm[3] = (const float*)d_in[10]; bm[3] = (const float*)d_in[11];
    } else {
        x[0]  = (const float*)d_in[0];  x[1]  = (const float*)d_in[1];
        x[2]  = (const float*)d_in[2];  x[3]  = (const float*)d_in[3];
        Wm[0] = (const float*)d_in[4];  bm[0] = (const float*)d_in[5];
        Wm[1] = (const float*)d_in[6];  bm[1] = (const float*)d_in[7];
        Wm[2] = (const float*)d_in[8];  bm[2] = (const float*)d_in[9];
        Wm[3] = (const float*)d_in[10]; bm[3] = (const float*)d_in[11];
    }
    mod_emb = (const float*)d_in[12];
    Wq = (const float*)d_in[13]; bq = (const float*)d_in[14];
    Wk = (const float*)d_in[15]; bk = (const float*)d_in[16];
    Wv = (const float*)d_in[17]; bv = (const float*)d_in[18];
    Wo = (const float*)d_in[19]; bo = (const float*)d_in[20];
    temp = (const float*)d_in[21];

    __half *xs1, *ws1, *ws2, *sb1, *fb1, *Qh, *Kh, *Vh;
    cudaGetSymbolAddress((void**)&xs1, g_xs1);
    cudaGetSymbolAddress((void**)&ws1, g_ws1);
    cudaGetSymbolAddress((void**)&ws2, g_ws2);
    cudaGetSymbolAddress((void**)&sb1, g_sb1);
    cudaGetSymbolAddress((void**)&Qh,  g_Qh);
    cudaGetSymbolAddress((void**)&Kh,  g_Kh);
    cudaGetSymbolAddress((void**)&Vh,  g_Vh);
    cudaGetSymbolAddress((void**)&fb1, g_fb1);

    // Persistent function attributes; set once outside graph capture.
    static bool attrSet = false;
    if (!attrSet) {
        cudaFuncSetAttribute(gemm_one,  cudaFuncAttributeMaxDynamicSharedMemorySize, NSTAGE * STAGE2);
        cudaFuncSetAttribute(gemm_qk,   cudaFuncAttributeMaxDynamicSharedMemorySize, NSTAGE * STAGE1);
        cudaFuncSetAttribute(gemm_v,    cudaFuncAttributeMaxDynamicSharedMemorySize, NSTAGE * STAGE2);
        cudaFuncSetAttribute(gemm_proj, cudaFuncAttributeMaxDynamicSharedMemorySize, NSTAGE * STAGE1);
        attrSet = true;
    }

    const int sls[4] = {2048, 1024, 1500, 512};
    const int kds[4] = {768, 1024, 512, 2048};
    const size_t xoff[4] = {0, 6291456, 10485760, 13631488};
    const size_t woff[4] = {0, 786432, 1835008, 2359296};
    const size_t wqkvo[4] = {4456448, 5505024, 6553600, 7602176};
    const long moff[4] = {0, 8192, 12288, 18288};
    const int blkStart[4] = {0, 64, 96, 143};   // cumulative 128-row blocks

    // 1) ALL converts/splits in one launch (1024 float4 per block):
    //    jobs 0-3: x -> fp16 hi;  4-7: Wm -> fp16 hi;  8-11: Wq/k/v/o -> hi+lo
    {
        ConvJobs cj;
        int blocks = 0;
        const float* wsrc[4] = {Wq, Wk, Wv, Wo};
        for (int m = 0; m < 4; ++m) {
            int n4 = (int)(((size_t)Bb * sls[m] * kds[m]) / 4);
            cj.src[m] = (const float4*)x[m];
            cj.d1[m]  = (__half2*)(xs1 + xoff[m]);
            cj.d2[m]  = nullptr;
            cj.start[m] = blocks;
            blocks += n4 / 1024;
        }
        for (int m = 0; m < 4; ++m) {
            int n4 = (int)(((size_t)1024 * kds[m]) / 4);
            cj.src[4 + m] = (const float4*)Wm[m];
            cj.d1[4 + m]  = (__half2*)(ws1 + woff[m]);
            cj.d2[4 + m]  = nullptr;
            cj.start[4 + m] = blocks;
            blocks += n4 / 1024;
        }
        for (int i = 0; i < 4; ++i) {
            cj.src[8 + i] = (const float4*)wsrc[i];
            cj.d1[8 + i]  = (__half2*)(ws1 + wqkvo[i]);
            cj.d2[8 + i]  = (__half2*)(ws2 + wqkvo[i]);
            cj.start[8 + i] = blocks;
            blocks += (1048576 / 4) / 1024;
        }
        cj.start[12] = blocks;
        conv_all<<<blocks, 256>>>(cj);
    }

    // 2) modality projections, ONE launch, 1-term -> compact fp16 stacked
    {
        Jobs4 jobs;
        for (int m = 0; m < 4; ++m) {
            jobs.j[m].A1   = xs1 + xoff[m];
            jobs.j[m].W1   = ws1 + woff[m];
            jobs.j[m].bias = bm[m];
            jobs.j[m].extra = mod_emb + m * Dd;
            jobs.j[m].o1   = sb1 + moff[m] * Dd;
            jobs.j[m].R    = Bb * sls[m];
            jobs.j[m].Kd   = kds[m];
            jobs.j[m].blkStart = blkStart[m];
        }
        dim3 grid(4, 159);
        gemm_proj<<<grid, 512, NSTAGE * STAGE1>>>(jobs);
    }

    // 3a) Q+K projection: 1-term, homogeneous launch (fp16 out)
    {
        dim3 grid(8, (RTOT + 127) / 128);
        gemm_qk<<<grid, 512, NSTAGE * STAGE1>>>(sb1, ws1 + wqkvo[0],
                                                bq, bk, Qh, Kh, RTOT);
    }
    // 3b) V projection: 2-term (fp16 out)
    {
        dim3 grid(4, (RTOT + 127) / 128);
        gemm_v<<<grid, 512, NSTAGE * STAGE2>>>(sb1, ws1 + wqkvo[0], ws2 + wqkvo[0],
                                               bv, Vh, RTOT);
    }

    // 4) routed attention + modality mean -> fp16 fused (2 heads/warp)
    attn_kernel<<<Bb * Ss, 256>>>(Qh, Kh, Vh, temp, fb1);

    // 5) output projection -> d_out (fp32, 2-term)
    {
        int R = Bb * Ss;   // 8192
        dim3 grid(4, R / 128);
        gemm_one<<<grid, 512, NSTAGE * STAGE2>>>(fb1, ws1 + wqkvo[3], ws2 + wqkvo[3],
                                                 bo, (float*)d_out, R, Dd);
    }
}

// round 16
// speedup vs baseline: 1.1557x; 1.1557x over previous
#include <cuda_runtime.h>
#include <cuda_fp16.h>
#include <math.h>
#include <stdint.h>

// Problem constants
#define Bb 4
#define Ss 2048
#define Dd 1024
#define Mm 4

// Compact row layout: per modality m, rows [moff[m], moff[m]+4*sl[m])
// sl = {2048,1024,1500,512}; moff = {0, 8192, 12288, 18288}; total 20336 rows.
#define RTOT 20336

// ---------------------------------------------------------------------------
// Device-global scratch (allocation-free rule)
__device__ __align__(16) __half g_xs1[17825792];   // x inputs, fp16 hi only
__device__ __align__(16) __half g_ws1[8650752];    // weights hi
__device__ __align__(16) __half g_ws2[8650752];    // weights lo (QKV/O region only)
__device__ __align__(16) __half g_sb1[20824064];   // compact stacked, fp16 hi
__device__ __align__(16) __half g_Qh[20824064];    // compact Q, fp16
__device__ __align__(16) __half g_Kh[20824064];    // compact K, fp16
__device__ __align__(16) __half g_Vh[20824064];    // compact V, fp16
__device__ __align__(16) __half g_fb1[8388608];    // fused (B,S,D), fp16 hi

// ---------------------------------------------------------------------------
// Batched fp32 -> fp16 convert/split: 12 jobs in one launch, 4 float4/thread.
struct ConvJobs {
    const float4* src[12];
    __half2*      d1[12];
    __half2*      d2[12];    // nullptr -> hi-only convert
    int           start[13]; // block-index prefix (1024 float4 per block)
};

__global__ __launch_bounds__(256)
void conv_all(ConvJobs jobs) {
    int blk = blockIdx.x;
    int j = 0;
    #pragma unroll
    for (int i = 1; i < 12; ++i)
        if (blk >= jobs.start[i]) j = i;
    int base = (blk - jobs.start[j]) * 1024 + threadIdx.x;

    const float4* src = jobs.src[j];
    float4 v[4];
    #pragma unroll
    for (int u = 0; u < 4; ++u) v[u] = src[base + 256 * u];

    __half2* d1 = jobs.d1[j];
    __half2* d2 = jobs.d2[j];
    #pragma unroll
    for (int u = 0; u < 4; ++u) {
        int i4 = base + 256 * u;
        __half h0 = __float2half_rn(v[u].x);
        __half h1 = __float2half_rn(v[u].y);
        __half h2 = __float2half_rn(v[u].z);
        __half h3 = __float2half_rn(v[u].w);
        d1[2*i4]   = __halves2half2(h0, h1);
        d1[2*i4+1] = __halves2half2(h2, h3);
        if (d2) {
            __half l0 = __float2half_rn(v[u].x - __half2float(h0));
            __half l1 = __float2half_rn(v[u].y - __half2float(h1));
            __half l2 = __float2half_rn(v[u].z - __half2float(h2));
            __half l3 = __float2half_rn(v[u].w - __half2float(h3));
            d2[2*i4]   = __halves2half2(l0, l1);
            d2[2*i4+1] = __halves2half2(l2, l3);
        }
    }
}

// ---------------------------------------------------------------------------
// fp16 split GEMM body (mma.sync m16n8k16), BM=128 x BN=128, BK=32,
// 256 threads, 2 CTAs/SM (cross-CTA overlap hides per-tile stall exposure —
// R14 lesson: 1 CTA/SM BN=256 regressed 15%).
// Template: NST = pipeline stages (4 for 1-term, 3 for 2-term);
//           TWO = W-lo term present.
// Stage layout: A @0 (10240 B), Wh @ARRB, [Wl @2*ARRB]. Bit-identical math
// to the R13 reference version.

#define ROWB 80                      // smem row stride bytes (conflict-free)
#define ARRB (128 * ROWB)            // 10240 bytes per operand array

__device__ __forceinline__ void mma_fp16(float* c, const unsigned* a, const unsigned* b) {
    asm volatile(
        "mma.sync.aligned.m16n8k16.row.col.f32.f16.f16.f32 "
        "{%0,%1,%2,%3}, {%4,%5,%6,%7}, {%8,%9}, {%0,%1,%2,%3};\n"
        : "+f"(c[0]), "+f"(c[1]), "+f"(c[2]), "+f"(c[3])
        : "r"(a[0]), "r"(a[1]), "r"(a[2]), "r"(a[3]), "r"(b[0]), "r"(b[1]));
}

__device__ __forceinline__ void ldsm4(unsigned& r0, unsigned& r1, unsigned& r2, unsigned& r3,
                                      unsigned addr) {
    asm volatile("ldmatrix.sync.aligned.m8n8.x4.shared.b16 {%0,%1,%2,%3}, [%4];"
                 : "=r"(r0), "=r"(r1), "=r"(r2), "=r"(r3) : "r"(addr));
}

__device__ __forceinline__ void cp16(unsigned dst, const void* src, bool valid) {
    int sz = valid ? 16 : 0;
    asm volatile("cp.async.cg.shared.global [%0], [%1], 16, %2;\n"
                 :: "r"(dst), "l"(src), "r"(sz));
}

template<int NST, bool TWO>
__device__ __forceinline__
void gemm_body(const __half* __restrict__ A1,
               const __half* __restrict__ W1, const __half* __restrict__ W2,
               const float* __restrict__ bias, const float* __restrict__ extra,
               float* __restrict__ outF, __half* __restrict__ o1,
               int R, int Kd, int row0, int wcol0, int ocol0)
{
    constexpr int STB = TWO ? (3 * ARRB) : (2 * ARRB);

    extern __shared__ __align__(16) char smem[];
    const unsigned smem32 = (unsigned)__cvta_generic_to_shared(smem);

    const int tid  = threadIdx.x;
    const int warp = tid >> 5;
    const int lane = tid & 31;
    const int wm = (warp >> 2) * 64;
    const int wn = (warp & 3) * 32;

    const int r0c = tid >> 2,         k0c = tid & 3;
    const int r1c = (tid + 256) >> 2, k1c = tid & 3;

    const int lane7 = lane & 7;
    const int j     = lane >> 3;
    const int aRow  = (j & 1) * 8 + lane7;
    const int aKb   = (j >> 1) * 16;
    const int bRow  = (j >> 1) * 8 + lane7;
    const int bKb   = (j & 1) * 16;

    float acc[4][4][4];
    #pragma unroll
    for (int i = 0; i < 4; ++i)
        #pragma unroll
        for (int k = 0; k < 4; ++k)
            #pragma unroll
            for (int l = 0; l < 4; ++l) acc[i][k][l] = 0.f;

    const int nT = Kd >> 5;   // BK = 32

    auto load_tile = [&](int t) {
        unsigned sb = smem32 + (t % NST) * STB;
        int kt = t << 5;
        {
            bool v0 = (row0 + r0c) < R;
            bool v1 = (row0 + r1c) < R;
            size_t sr0 = v0 ? (size_t)(row0 + r0c) : 0;
            size_t sr1 = v1 ? (size_t)(row0 + r1c) : 0;
            cp16(sb + 0*ARRB + r0c*ROWB + k0c*16, A1 + sr0*Kd + kt + k0c*8, v0);
            cp16(sb + 0*ARRB + r1c*ROWB + k1c*16, A1 + sr1*Kd + kt + k1c*8, v1);
        }
        {
            size_t sr0 = (size_t)(wcol0 + r0c);
            size_t sr1 = (size_t)(wcol0 + r1c);
            cp16(sb + 1*ARRB + r0c*ROWB + k0c*16, W1 + sr0*Kd + kt + k0c*8, true);
            cp16(sb + 1*ARRB + r1c*ROWB + k1c*16, W1 + sr1*Kd + kt + k1c*8, true);
            if (TWO) {
                cp16(sb + 2*ARRB + r0c*ROWB + k0c*16, W2 + sr0*Kd + kt + k0c*8, true);
                cp16(sb + 2*ARRB + r1c*ROWB + k1c*16, W2 + sr1*Kd + kt + k1c*8, true);
            }
        }
    };

    #pragma unroll
    for (int p = 0; p < NST - 1; ++p) {
        if (p < nT) {
            load_tile(p);
            asm volatile("cp.async.commit_group;" ::: "memory");
        }
    }

    for (int t = 0; t < nT; ++t) {
        // wait until tile t's group is complete
        if (t + NST - 2 < nT)      asm volatile("cp.async.wait_group %0;" :: "n"(NST - 2) : "memory");
        else if (t + 1 < nT)       asm volatile("cp.async.wait_group 1;" ::: "memory");
        else                       asm volatile("cp.async.wait_group 0;" ::: "memory");
        __syncthreads();
        if (t + NST - 1 < nT) {
            load_tile(t + NST - 1);
            asm volatile("cp.async.commit_group;" ::: "memory");
        }
        const unsigned s0 = smem32 + (t % NST) * STB;

        #pragma unroll
        for (int ks = 0; ks < 2; ++ks) {
            const int kb = ks * 32;
            unsigned a[4][4], bH[4][2], bL[4][2];
            #pragma unroll
            for (int mt = 0; mt < 4; ++mt)
                ldsm4(a[mt][0], a[mt][1], a[mt][2], a[mt][3],
                      s0 + 0*ARRB + (unsigned)(wm + mt*16 + aRow) * ROWB + kb + aKb);
            #pragma unroll
            for (int np = 0; np < 2; ++np) {
                unsigned r0, r1, r2, r3;
                ldsm4(r0, r1, r2, r3,
                      s0 + 1*ARRB + (unsigned)(wn + np*16 + bRow) * ROWB + kb + bKb);
                bH[np*2][0] = r0; bH[np*2][1] = r1; bH[np*2+1][0] = r2; bH[np*2+1][1] = r3;
            }
            if (TWO) {
                #pragma unroll
                for (int np = 0; np < 2; ++np) {
                    unsigned r0, r1, r2, r3;
                    ldsm4(r0, r1, r2, r3,
                          s0 + 2*ARRB + (unsigned)(wn + np*16 + bRow) * ROWB + kb + bKb);
                    bL[np*2][0] = r0; bL[np*2][1] = r1; bL[np*2+1][0] = r2; bL[np*2+1][1] = r3;
                }
            }
            #pragma unroll
            for (int mt = 0; mt < 4; ++mt)
                #pragma unroll
                for (int nt = 0; nt < 4; ++nt)
                    mma_fp16(acc[mt][nt], a[mt], bH[nt]);
            if (TWO) {
                #pragma unroll
                for (int mt = 0; mt < 4; ++mt)
                    #pragma unroll
                    for (int nt = 0; nt < 4; ++nt)
                        mma_fp16(acc[mt][nt], a[mt], bL[nt]);
            }
        }
    }

    // ---- epilogue (contiguous rows; hi-only fp16 or fp32)
    const int tg = lane >> 2;
    const int tc = 2 * (lane & 3);
    #pragma unroll
    for (int mt = 0; mt < 4; ++mt) {
        #pragma unroll
        for (int half_ = 0; half_ < 2; ++half_) {
            int r = row0 + wm + mt*16 + tg + half_*8;
            if (r >= R) continue;
            long rowIdx = (long)r * 1024;
            #pragma unroll
            for (int nt = 0; nt < 4; ++nt) {
                int c = ocol0 + wn + nt*8 + tc;
                float v0 = acc[mt][nt][half_*2 + 0] + bias[c];
                float v1 = acc[mt][nt][half_*2 + 1] + bias[c + 1];
                if (extra) { v0 += extra[c]; v1 += extra[c + 1]; }
                if (outF) {
                    *(float2*)(outF + rowIdx + c) = make_float2(v0, v1);
                } else {
                    *(__half2*)(o1 + rowIdx + c) =
                        __halves2half2(__float2half_rn(v0), __float2half_rn(v1));
                }
            }
        }
    }
}

// ---------------------------------------------------------------------------
// Output projection -> fp32 d_out, 2-term, 3-stage. grid (8, 64).
__global__ __launch_bounds__(256, 2)
void gemm_one(const __half* __restrict__ A1,
              const __half* __restrict__ W1, const __half* __restrict__ W2,
              const float* __restrict__ bias, float* __restrict__ outF,
              int R, int Kd)
{
    int col0 = blockIdx.x * 128;
    gemm_body<3, true>(A1, W1, W2, bias, nullptr, outF, nullptr,
                       R, Kd, blockIdx.y * 128, col0, col0);
}

// Q+K projection, 1-TERM, 4-stage, homogeneous. grid (16, 159).
__global__ __launch_bounds__(256, 2)
void gemm_qk(const __half* __restrict__ A1, const __half* __restrict__ W1,
             const float* __restrict__ b0, const float* __restrict__ b1,
             __half* __restrict__ Qh, __half* __restrict__ Kh, int R)
{
    int wcol0 = blockIdx.x * 128;           // 0..1920
    int cblk  = wcol0 >> 10;                // 0=Q 1=K (uniform per CTA)
    int row0  = blockIdx.y * 128;
    int ocol0 = wcol0 & 1023;
    const float* bias = (cblk == 0) ? b0 : b1;
    __half* out       = (cblk == 0) ? Qh : Kh;
    gemm_body<4, false>(A1, W1, nullptr, bias, nullptr, nullptr, out,
                        R, 1024, row0, wcol0, ocol0);
}

// V projection, 2-term, 3-stage, fp16 store. grid (8, 159).
__global__ __launch_bounds__(256, 2)
void gemm_v(const __half* __restrict__ A1,
            const __half* __restrict__ W1, const __half* __restrict__ W2,
            const float* __restrict__ bias, __half* __restrict__ Vh, int R)
{
    int wcol0 = 2048 + blockIdx.x * 128;    // V rows of W arena
    gemm_body<3, true>(A1, W1, W2, bias, nullptr, nullptr, Vh,
                       R, 1024, blockIdx.y * 128, wcol0, wcol0 & 1023);
}

// Merged modality projections: 4 jobs, grid (8, 159), 1-TERM, 4-stage.
struct GemmJob {
    const __half *A1, *W1;
    const float *bias, *extra;
    __half *o1;
    int R, Kd, blkStart;
};
struct Jobs4 { GemmJob j[4]; };

__global__ __launch_bounds__(256, 2)
void gemm_proj(Jobs4 jobs)
{
    int by = blockIdx.y;
    GemmJob jb = jobs.j[0];
    if (by >= jobs.j[1].blkStart) jb = jobs.j[1];
    if (by >= jobs.j[2].blkStart) jb = jobs.j[2];
    if (by >= jobs.j[3].blkStart) jb = jobs.j[3];
    int row0 = (by - jb.blkStart) * 128;
    int col0 = blockIdx.x * 128;
    gemm_body<4, false>(jb.A1, jb.W1, nullptr, jb.bias, jb.extra, nullptr, jb.o1,
                        jb.R, jb.Kd, row0, col0, col0);
}

// ---------------------------------------------------------------------------
// Routed per-position attention + modality mean over COMPACT Q/K/V (all fp16).
// ROUTES (compile-time, replicates reference float64 Cantor math incl. ties):
//   [[0,1,2],[0,1,2],[2,3,0],[3,2,0]]
// Padded positions (s >= sl[m]) substitute zeros.
// 256 threads/block: warp handles 2 heads (16 lanes each, half4 lanes).
__global__ __launch_bounds__(256)
void attn_kernel(const __half* __restrict__ Q, const __half* __restrict__ K,
                 const __half* __restrict__ V, const float* __restrict__ tptr,
                 __half* __restrict__ f1)
{
    const int routes[4][3] = {{0,1,2},{0,1,2},{2,3,0},{3,2,0}};
    const int sls[4]  = {2048, 1024, 1500, 512};
    const int moff[4] = {0, 8192, 12288, 18288};

    int bs   = blockIdx.x;
    int b    = bs >> 11;
    int s    = bs & (Ss - 1);
    int warp = threadIdx.x >> 5;      // 0..7 -> heads 2w, 2w+1
    int lane = threadIdx.x & 31;
    int sub  = lane >> 4;             // which head of the pair
    int l16  = lane & 15;
    int h    = warp * 2 + sub;

    const float scale = 1.0f / (8.0f * fabsf(*tptr));
    const int lo = h * 64 + l16 * 4;  // element offset of this lane's 4 elems

    long off[4];
    bool valid[4];
    #pragma unroll
    for (int m = 0; m < 4; ++m) {
        valid[m] = (s < sls[m]);
        off[m] = valid[m] ? (((long)moff[m] + (long)b * sls[m] + s) * Dd + lo) : 0;
    }

    // Load each distinct Q/K/V vector exactly once (half4 -> float4)
    float4 q[4], k[4], v[4];
    #pragma unroll
    for (int m = 0; m < 4; ++m) {
        if (valid[m]) {
            __half2 a0 = *(const __half2*)(Q + off[m]);
            __half2 a1 = *(const __half2*)(Q + off[m] + 2);
            float2 fa = __half22float2(a0), fb = __half22float2(a1);
            q[m] = make_float4(fa.x, fa.y, fb.x, fb.y);
            a0 = *(const __half2*)(K + off[m]);
            a1 = *(const __half2*)(K + off[m] + 2);
            fa = __half22float2(a0); fb = __half22float2(a1);
            k[m] = make_float4(fa.x, fa.y, fb.x, fb.y);
            a0 = *(const __half2*)(V + off[m]);
            a1 = *(const __half2*)(V + off[m] + 2);
            fa = __half22float2(a0); fb = __half22float2(a1);
            v[m] = make_float4(fa.x, fa.y, fb.x, fb.y);
        } else {
            q[m] = make_float4(0.f, 0.f, 0.f, 0.f);
            k[m] = q[m];
            v[m] = q[m];
        }
    }

    // 12 partial dots, then butterfly-reduce within each 16-lane head group
    float d[4][3];
    #pragma unroll
    for (int m = 0; m < 4; ++m)
        #pragma unroll
        for (int jj = 0; jj < 3; ++jj) {
            const float4 kk = k[routes[m][jj]];
            d[m][jj] = q[m].x*kk.x + q[m].y*kk.y + q[m].z*kk.z + q[m].w*kk.w;
        }
    #pragma unroll
    for (int offs = 8; offs > 0; offs >>= 1)
        #pragma unroll
        for (int m = 0; m < 4; ++m)
            #pragma unroll
            for (int jj = 0; jj < 3; ++jj)
                d[m][jj] += __shfl_xor_sync(0xffffffffu, d[m][jj], offs);

    // Softmax per m + weighted V accumulation
    float4 acc = make_float4(0.f, 0.f, 0.f, 0.f);
    #pragma unroll
    for (int m = 0; m < 4; ++m) {
        float sc0 = d[m][0] * scale;
        float sc1 = d[m][1] * scale;
        float sc2 = d[m][2] * scale;
        float mx = fmaxf(sc0, fmaxf(sc1, sc2));
        float e0 = expf(sc0 - mx);
        float e1 = expf(sc1 - mx);
        float e2 = expf(sc2 - mx);
        float inv = 1.0f / (e0 + e1 + e2);
        float a0 = e0 * inv, a1 = e1 * inv, a2 = e2 * inv;
        const float4 v0 = v[routes[m][0]];
        const float4 v1 = v[routes[m][1]];
        const float4 v2 = v[routes[m][2]];
        acc.x += a0 * v0.x + a1 * v1.x + a2 * v2.x;
        acc.y += a0 * v0.y + a1 * v1.y + a2 * v2.y;
        acc.z += a0 * v0.z + a1 * v1.z + a2 * v2.z;
        acc.w += a0 * v0.w + a1 * v1.w + a2 * v2.w;
    }

    long o = ((long)b * Ss + s) * Dd + lo;
    __half2 p0 = __floats2half2_rn(acc.x * 0.25f, acc.y * 0.25f);
    __half2 p1 = __floats2half2_rn(acc.z * 0.25f, acc.w * 0.25f);
    uint2 pk;
    pk.x = *(unsigned*)&p0;
    pk.y = *(unsigned*)&p1;
    *(uint2*)(f1 + o) = pk;
}

// ---------------------------------------------------------------------------
extern "C" void kernel_launch(void* const* d_in, const int* in_sizes, int n_in,
                              void* d_out, int out_size)
{
    const float *x[4], *Wm[4], *bm[4];
    const float *mod_emb, *Wq, *bq, *Wk, *bk, *Wv, *bv, *Wo, *bo, *temp;

    if (in_sizes[1] == 786432) {
        x[0]  = (const float*)d_in[0];  Wm[0] = (const float*)d_in[1];  bm[0] = (const float*)d_in[2];
        x[1]  = (const float*)d_in[3];  Wm[1] = (const float*)d_in[4];  bm[1] = (const float*)d_in[5];
        x[2]  = (const float*)d_in[6];  Wm[2] = (const float*)d_in[7];  bm[2] = (const float*)d_in[8];
        x[3]  = (const float*)d_in[9];  Wm[3] = (const float*)d_in[10]; bm[3] = (const float*)d_in[11];
    } else {
        x[0]  = (const float*)d_in[0];  x[1]  = (const float*)d_in[1];
        x[2]  = (const float*)d_in[2];  x[3]  = (const float*)d_in[3];
        Wm[0] = (const float*)d_in[4];  bm[0] = (const float*)d_in[5];
        Wm[1] = (const float*)d_in[6];  bm[1] = (const float*)d_in[7];
        Wm[2] = (const float*)d_in[8];  bm[2] = (const float*)d_in[9];
        Wm[3] = (const float*)d_in[10]; bm[3] = (const float*)d_in[11];
    }
    mod_emb = (const float*)d_in[12];
    Wq = (const float*)d_in[13]; bq = (const float*)d_in[14];
    Wk = (const float*)d_in[15]; bk = (const float*)d_in[16];
    Wv = (const float*)d_in[17]; bv = (const float*)d_in[18];
    Wo = (const float*)d_in[19]; bo = (const float*)d_in[20];
    temp = (const float*)d_in[21];

    __half *xs1, *ws1, *ws2, *sb1, *fb1, *Qh, *Kh, *Vh;
    cudaGetSymbolAddress((void**)&xs1, g_xs1);
    cudaGetSymbolAddress((void**)&ws1, g_ws1);
    cudaGetSymbolAddress((void**)&ws2, g_ws2);
    cudaGetSymbolAddress((void**)&sb1, g_sb1);
    cudaGetSymbolAddress((void**)&Qh,  g_Qh);
    cudaGetSymbolAddress((void**)&Kh,  g_Kh);
    cudaGetSymbolAddress((void**)&Vh,  g_Vh);
    cudaGetSymbolAddress((void**)&fb1, g_fb1);

    // Persistent function attributes; set once outside graph capture.
    static bool attrSet = false;
    if (!attrSet) {
        cudaFuncSetAttribute(gemm_one,  cudaFuncAttributeMaxDynamicSharedMemorySize, 3 * 3 * ARRB);
        cudaFuncSetAttribute(gemm_qk,   cudaFuncAttributeMaxDynamicSharedMemorySize, 4 * 2 * ARRB);
        cudaFuncSetAttribute(gemm_v,    cudaFuncAttributeMaxDynamicSharedMemorySize, 3 * 3 * ARRB);
        cudaFuncSetAttribute(gemm_proj, cudaFuncAttributeMaxDynamicSharedMemorySize, 4 * 2 * ARRB);
        attrSet = true;
    }

    const int sls[4] = {2048, 1024, 1500, 512};
    const int kds[4] = {768, 1024, 512, 2048};
    const size_t xoff[4] = {0, 6291456, 10485760, 13631488};
    const size_t woff[4] = {0, 786432, 1835008, 2359296};
    const size_t wqkvo[4] = {4456448, 5505024, 6553600, 7602176};
    const long moff[4] = {0, 8192, 12288, 18288};
    const int blkStart[4] = {0, 64, 96, 143};   // cumulative 128-row blocks

    // 1) ALL converts/splits in one launch (1024 float4 per block):
    //    jobs 0-3: x -> fp16 hi;  4-7: Wm -> fp16 hi;  8-11: Wq/k/v/o -> hi+lo
    {
        ConvJobs cj;
        int blocks = 0;
        const float* wsrc[4] = {Wq, Wk, Wv, Wo};
        for (int m = 0; m < 4; ++m) {
            int n4 = (int)(((size_t)Bb * sls[m] * kds[m]) / 4);
            cj.src[m] = (const float4*)x[m];
            cj.d1[m]  = (__half2*)(xs1 + xoff[m]);
            cj.d2[m]  = nullptr;
            cj.start[m] = blocks;
            blocks += n4 / 1024;
        }
        for (int m = 0; m < 4; ++m) {
            int n4 = (int)(((size_t)1024 * kds[m]) / 4);
            cj.src[4 + m] = (const float4*)Wm[m];
            cj.d1[4 + m]  = (__half2*)(ws1 + woff[m]);
            cj.d2[4 + m]  = nullptr;
            cj.start[4 + m] = blocks;
            blocks += n4 / 1024;
        }
        for (int i = 0; i < 4; ++i) {
            cj.src[8 + i] = (const float4*)wsrc[i];
            cj.d1[8 + i]  = (__half2*)(ws1 + wqkvo[i]);
            cj.d2[8 + i]  = (__half2*)(ws2 + wqkvo[i]);
            cj.start[8 + i] = blocks;
            blocks += (1048576 / 4) / 1024;
        }
        cj.start[12] = blocks;
        conv_all<<<blocks, 256>>>(cj);
    }

    // 2) modality projections, ONE launch, 1-term, 4-stage
    {
        Jobs4 jobs;
        for (int m = 0; m < 4; ++m) {
            jobs.j[m].A1   = xs1 + xoff[m];
            jobs.j[m].W1   = ws1 + woff[m];
            jobs.j[m].bias = bm[m];
            jobs.j[m].extra = mod_emb + m * Dd;
            jobs.j[m].o1   = sb1 + moff[m] * Dd;
            jobs.j[m].R    = Bb * sls[m];
            jobs.j[m].Kd   = kds[m];
            jobs.j[m].blkStart = blkStart[m];
        }
        dim3 grid(8, 159);
        gemm_proj<<<grid, 256, 4 * 2 * ARRB>>>(jobs);
    }

    // 3a) Q+K projection: 1-term, 4-stage, homogeneous launch (fp16 out)
    {
        dim3 grid(16, (RTOT + 127) / 128);
        gemm_qk<<<grid, 256, 4 * 2 * ARRB>>>(sb1, ws1 + wqkvo[0],
                                             bq, bk, Qh, Kh, RTOT);
    }
    // 3b) V projection: 2-term, 3-stage (fp16 out)
    {
        dim3 grid(8, (RTOT + 127) / 128);
        gemm_v<<<grid, 256, 3 * 3 * ARRB>>>(sb1, ws1 + wqkvo[0], ws2 + wqkvo[0],
                                            bv, Vh, RTOT);
    }

    // 4) routed attention + modality mean -> fp16 fused (2 heads/warp)
    attn_kernel<<<Bb * Ss, 256>>>(Qh, Kh, Vh, temp, fb1);

    // 5) output projection -> d_out (fp32, 2-term, 3-stage)
    {
        int R = Bb * Ss;   // 8192
        dim3 grid(8, R / 128);
        gemm_one<<<grid, 256, 3 * 3 * ARRB>>>(fb1, ws1 + wqkvo[3], ws2 + wqkvo[3],
                                              bo, (float*)d_out, R, Dd);
    }
}

// round 17
// speedup vs baseline: 1.2964x; 1.1218x over previous
#include <cuda_runtime.h>
#include <cuda_fp16.h>
#include <math.h>
#include <stdint.h>

// Problem constants
#define Bb 4
#define Ss 2048
#define Dd 1024
#define Mm 4

// Compact row layout: per modality m, rows [moff[m], moff[m]+4*sl[m])
// sl = {2048,1024,1500,512}; moff = {0, 8192, 12288, 18288}; total 20336 rows.
#define RTOT 20336

// ---------------------------------------------------------------------------
// Device-global scratch (allocation-free rule)
__device__ __align__(16) __half g_xs1[17825792];   // x inputs, fp16 hi only
__device__ __align__(16) __half g_ws1[8650752];    // weights hi
__device__ __align__(16) __half g_ws2[8650752];    // weights lo (QKV/O region only)
__device__ __align__(16) __half g_sb1[20824064];   // compact stacked, fp16 hi
__device__ __align__(16) __half g_Qh[20824064];    // compact Q, fp16
__device__ __align__(16) __half g_Kh[20824064];    // compact K, fp16
__device__ __align__(16) __half g_Vh[20824064];    // compact V, fp16
__device__ __align__(16) __half g_fb1[8388608];    // fused (B,S,D), fp16 hi

// ---------------------------------------------------------------------------
// Batched fp32 -> fp16 convert/split: 12 jobs in one launch, 4 float4/thread.
struct ConvJobs {
    const float4* src[12];
    __half2*      d1[12];
    __half2*      d2[12];    // nullptr -> hi-only convert
    int           start[13]; // block-index prefix (1024 float4 per block)
};

__global__ __launch_bounds__(256)
void conv_all(ConvJobs jobs) {
    int blk = blockIdx.x;
    int j = 0;
    #pragma unroll
    for (int i = 1; i < 12; ++i)
        if (blk >= jobs.start[i]) j = i;
    int base = (blk - jobs.start[j]) * 1024 + threadIdx.x;

    const float4* src = jobs.src[j];
    float4 v[4];
    #pragma unroll
    for (int u = 0; u < 4; ++u) v[u] = src[base + 256 * u];

    __half2* d1 = jobs.d1[j];
    __half2* d2 = jobs.d2[j];
    #pragma unroll
    for (int u = 0; u < 4; ++u) {
        int i4 = base + 256 * u;
        __half h0 = __float2half_rn(v[u].x);
        __half h1 = __float2half_rn(v[u].y);
        __half h2 = __float2half_rn(v[u].z);
        __half h3 = __float2half_rn(v[u].w);
        d1[2*i4]   = __halves2half2(h0, h1);
        d1[2*i4+1] = __halves2half2(h2, h3);
        if (d2) {
            __half l0 = __float2half_rn(v[u].x - __half2float(h0));
            __half l1 = __float2half_rn(v[u].y - __half2float(h1));
            __half l2 = __float2half_rn(v[u].z - __half2float(h2));
            __half l3 = __float2half_rn(v[u].w - __half2float(h3));
            d2[2*i4]   = __halves2half2(l0, l1);
            d2[2*i4+1] = __halves2half2(l2, l3);
        }
    }
}

// ---------------------------------------------------------------------------
// fp16 split GEMM body (mma.sync m16n8k16), BM=128 x BN=128, BK=64,
// 256 threads, 2 CTAs/SM. BK=64 halves the per-CTA tile count (and with it
// the fixed per-tile barrier/wait overhead) vs BK=32; smem traffic and MMA
// count per K unchanged; same k-order accumulation -> bit-identical results.
// Template: NST = pipeline stages (3 for 1-term, 2 for 2-term);
//           TWO = W-lo term present.
// Stage layout: A @0, Wh @ARR64, [Wl @2*ARR64]; rows 128B padded to 144B
// (ldsm rows hit distinct 4-bank groups: 36-bank row stride).

#define ROWB 144                     // smem row stride bytes (conflict-free)
#define ARR64 (128 * ROWB)           // 18432 bytes per operand array

__device__ __forceinline__ void mma_fp16(float* c, const unsigned* a, const unsigned* b) {
    asm volatile(
        "mma.sync.aligned.m16n8k16.row.col.f32.f16.f16.f32 "
        "{%0,%1,%2,%3}, {%4,%5,%6,%7}, {%8,%9}, {%0,%1,%2,%3};\n"
        : "+f"(c[0]), "+f"(c[1]), "+f"(c[2]), "+f"(c[3])
        : "r"(a[0]), "r"(a[1]), "r"(a[2]), "r"(a[3]), "r"(b[0]), "r"(b[1]));
}

__device__ __forceinline__ void ldsm4(unsigned& r0, unsigned& r1, unsigned& r2, unsigned& r3,
                                      unsigned addr) {
    asm volatile("ldmatrix.sync.aligned.m8n8.x4.shared.b16 {%0,%1,%2,%3}, [%4];"
                 : "=r"(r0), "=r"(r1), "=r"(r2), "=r"(r3) : "r"(addr));
}

__device__ __forceinline__ void cp16(unsigned dst, const void* src, bool valid) {
    int sz = valid ? 16 : 0;
    asm volatile("cp.async.cg.shared.global [%0], [%1], 16, %2;\n"
                 :: "r"(dst), "l"(src), "r"(sz));
}

template<int NST, bool TWO>
__device__ __forceinline__
void gemm_body(const __half* __restrict__ A1,
               const __half* __restrict__ W1, const __half* __restrict__ W2,
               const float* __restrict__ bias, const float* __restrict__ extra,
               float* __restrict__ outF, __half* __restrict__ o1,
               int R, int Kd, int row0, int wcol0, int ocol0)
{
    constexpr int STB = TWO ? (3 * ARR64) : (2 * ARR64);

    extern __shared__ __align__(16) char smem[];
    const unsigned smem32 = (unsigned)__cvta_generic_to_shared(smem);

    const int tid  = threadIdx.x;
    const int warp = tid >> 5;
    const int lane = tid & 31;
    const int wm = (warp >> 2) * 64;
    const int wn = (warp & 3) * 32;

    // loader mapping: per array 1024 16B-chunks; thread t does chunks
    // t+256u (u=0..3): row = (t>>3)+32u, col16 = t&7.
    const int lrow = tid >> 3;
    const int lcol = tid & 7;

    const int lane7 = lane & 7;
    const int j     = lane >> 3;
    const int aRow  = (j & 1) * 8 + lane7;
    const int aKb   = (j >> 1) * 16;
    const int bRow  = (j >> 1) * 8 + lane7;
    const int bKb   = (j & 1) * 16;

    float acc[4][4][4];
    #pragma unroll
    for (int i = 0; i < 4; ++i)
        #pragma unroll
        for (int k = 0; k < 4; ++k)
            #pragma unroll
            for (int l = 0; l < 4; ++l) acc[i][k][l] = 0.f;

    const int nT = Kd >> 6;   // BK = 64

    auto load_tile = [&](int t) {
        unsigned sb = smem32 + (t % NST) * STB;
        int kt = t << 6;
        #pragma unroll
        for (int u = 0; u < 4; ++u) {
            int r = lrow + 32 * u;
            unsigned soff = (unsigned)r * ROWB + lcol * 16;
            // A (row guard vs R)
            {
                bool v = (row0 + r) < R;
                size_t sr = v ? (size_t)(row0 + r) : 0;
                cp16(sb + soff, A1 + sr * Kd + kt + lcol * 8, v);
            }
            // W hi (and lo)
            {
                size_t sr = (size_t)(wcol0 + r);
                cp16(sb + ARR64 + soff, W1 + sr * Kd + kt + lcol * 8, true);
                if (TWO)
                    cp16(sb + 2*ARR64 + soff, W2 + sr * Kd + kt + lcol * 8, true);
            }
        }
    };

    #pragma unroll
    for (int p = 0; p < NST - 1; ++p) {
        if (p < nT) {
            load_tile(p);
            asm volatile("cp.async.commit_group;" ::: "memory");
        }
    }

    for (int t = 0; t < nT; ++t) {
        // leave the newest NST-2 committed groups outstanding -> tile t done
        asm volatile("cp.async.wait_group %0;" :: "n"(NST - 2) : "memory");
        __syncthreads();
        if (t + NST - 1 < nT) {
            load_tile(t + NST - 1);
            asm volatile("cp.async.commit_group;" ::: "memory");
        }
        const unsigned s0 = smem32 + (t % NST) * STB;

        #pragma unroll
        for (int ks = 0; ks < 4; ++ks) {
            const int kb = ks * 32;   // 16 halves per k16-step
            unsigned a[4][4], bH[4][2], bL[4][2];
            #pragma unroll
            for (int mt = 0; mt < 4; ++mt)
                ldsm4(a[mt][0], a[mt][1], a[mt][2], a[mt][3],
                      s0 + (unsigned)(wm + mt*16 + aRow) * ROWB + kb + aKb);
            #pragma unroll
            for (int np = 0; np < 2; ++np) {
                unsigned r0, r1, r2, r3;
                ldsm4(r0, r1, r2, r3,
                      s0 + ARR64 + (unsigned)(wn + np*16 + bRow) * ROWB + kb + bKb);
                bH[np*2][0] = r0; bH[np*2][1] = r1; bH[np*2+1][0] = r2; bH[np*2+1][1] = r3;
            }
            if (TWO) {
                #pragma unroll
                for (int np = 0; np < 2; ++np) {
                    unsigned r0, r1, r2, r3;
                    ldsm4(r0, r1, r2, r3,
                          s0 + 2*ARR64 + (unsigned)(wn + np*16 + bRow) * ROWB + kb + bKb);
                    bL[np*2][0] = r0; bL[np*2][1] = r1; bL[np*2+1][0] = r2; bL[np*2+1][1] = r3;
                }
            }
            #pragma unroll
            for (int mt = 0; mt < 4; ++mt)
                #pragma unroll
                for (int nt = 0; nt < 4; ++nt)
                    mma_fp16(acc[mt][nt], a[mt], bH[nt]);
            if (TWO) {
                #pragma unroll
                for (int mt = 0; mt < 4; ++mt)
                    #pragma unroll
                    for (int nt = 0; nt < 4; ++nt)
                        mma_fp16(acc[mt][nt], a[mt], bL[nt]);
            }
        }
    }

    // ---- epilogue (contiguous rows; hi-only fp16 or fp32)
    const int tg = lane >> 2;
    const int tc = 2 * (lane & 3);
    #pragma unroll
    for (int mt = 0; mt < 4; ++mt) {
        #pragma unroll
        for (int half_ = 0; half_ < 2; ++half_) {
            int r = row0 + wm + mt*16 + tg + half_*8;
            if (r >= R) continue;
            long rowIdx = (long)r * 1024;
            #pragma unroll
            for (int nt = 0; nt < 4; ++nt) {
                int c = ocol0 + wn + nt*8 + tc;
                float v0 = acc[mt][nt][half_*2 + 0] + bias[c];
                float v1 = acc[mt][nt][half_*2 + 1] + bias[c + 1];
                if (extra) { v0 += extra[c]; v1 += extra[c + 1]; }
                if (outF) {
                    *(float2*)(outF + rowIdx + c) = make_float2(v0, v1);
                } else {
                    *(__half2*)(o1 + rowIdx + c) =
                        __halves2half2(__float2half_rn(v0), __float2half_rn(v1));
                }
            }
        }
    }
}

// ---------------------------------------------------------------------------
// Output projection -> fp32 d_out, 2-term, 2-stage BK=64. grid (8, 64).
__global__ __launch_bounds__(256, 2)
void gemm_one(const __half* __restrict__ A1,
              const __half* __restrict__ W1, const __half* __restrict__ W2,
              const float* __restrict__ bias, float* __restrict__ outF,
              int R, int Kd)
{
    int col0 = blockIdx.x * 128;
    gemm_body<2, true>(A1, W1, W2, bias, nullptr, outF, nullptr,
                       R, Kd, blockIdx.y * 128, col0, col0);
}

// Q+K projection, 1-TERM, 3-stage BK=64, homogeneous. grid (16, 159).
__global__ __launch_bounds__(256, 2)
void gemm_qk(const __half* __restrict__ A1, const __half* __restrict__ W1,
             const float* __restrict__ b0, const float* __restrict__ b1,
             __half* __restrict__ Qh, __half* __restrict__ Kh, int R)
{
    int wcol0 = blockIdx.x * 128;           // 0..1920
    int cblk  = wcol0 >> 10;                // 0=Q 1=K (uniform per CTA)
    int row0  = blockIdx.y * 128;
    int ocol0 = wcol0 & 1023;
    const float* bias = (cblk == 0) ? b0 : b1;
    __half* out       = (cblk == 0) ? Qh : Kh;
    gemm_body<3, false>(A1, W1, nullptr, bias, nullptr, nullptr, out,
                        R, 1024, row0, wcol0, ocol0);
}

// V projection, 2-term, 2-stage BK=64, fp16 store. grid (8, 159).
__global__ __launch_bounds__(256, 2)
void gemm_v(const __half* __restrict__ A1,
            const __half* __restrict__ W1, const __half* __restrict__ W2,
            const float* __restrict__ bias, __half* __restrict__ Vh, int R)
{
    int wcol0 = 2048 + blockIdx.x * 128;    // V rows of W arena
    gemm_body<2, true>(A1, W1, W2, bias, nullptr, nullptr, Vh,
                       R, 1024, blockIdx.y * 128, wcol0, wcol0 & 1023);
}

// Merged modality projections: 4 jobs, grid (8, 159), 1-TERM, 3-stage BK=64.
struct GemmJob {
    const __half *A1, *W1;
    const float *bias, *extra;
    __half *o1;
    int R, Kd, blkStart;
};
struct Jobs4 { GemmJob j[4]; };

__global__ __launch_bounds__(256, 2)
void gemm_proj(Jobs4 jobs)
{
    int by = blockIdx.y;
    GemmJob jb = jobs.j[0];
    if (by >= jobs.j[1].blkStart) jb = jobs.j[1];
    if (by >= jobs.j[2].blkStart) jb = jobs.j[2];
    if (by >= jobs.j[3].blkStart) jb = jobs.j[3];
    int row0 = (by - jb.blkStart) * 128;
    int col0 = blockIdx.x * 128;
    gemm_body<3, false>(jb.A1, jb.W1, nullptr, jb.bias, jb.extra, nullptr, jb.o1,
                        jb.R, jb.Kd, row0, col0, col0);
}

// ---------------------------------------------------------------------------
// Routed per-position attention + modality mean over COMPACT Q/K/V (all fp16).
// ROUTES (compile-time, replicates reference float64 Cantor math incl. ties):
//   [[0,1,2],[0,1,2],[2,3,0],[3,2,0]]
// Padded positions (s >= sl[m]) substitute zeros.
// 256 threads/block: warp handles 2 heads (16 lanes each, half4 lanes).
__global__ __launch_bounds__(256)
void attn_kernel(const __half* __restrict__ Q, const __half* __restrict__ K,
                 const __half* __restrict__ V, const float* __restrict__ tptr,
                 __half* __restrict__ f1)
{
    const int routes[4][3] = {{0,1,2},{0,1,2},{2,3,0},{3,2,0}};
    const int sls[4]  = {2048, 1024, 1500, 512};
    const int moff[4] = {0, 8192, 12288, 18288};

    int bs   = blockIdx.x;
    int b    = bs >> 11;
    int s    = bs & (Ss - 1);
    int warp = threadIdx.x >> 5;      // 0..7 -> heads 2w, 2w+1
    int lane = threadIdx.x & 31;
    int sub  = lane >> 4;             // which head of the pair
    int l16  = lane & 15;
    int h    = warp * 2 + sub;

    const float scale = 1.0f / (8.0f * fabsf(*tptr));
    const int lo = h * 64 + l16 * 4;  // element offset of this lane's 4 elems

    long off[4];
    bool valid[4];
    #pragma unroll
    for (int m = 0; m < 4; ++m) {
        valid[m] = (s < sls[m]);
        off[m] = valid[m] ? (((long)moff[m] + (long)b * sls[m] + s) * Dd + lo) : 0;
    }

    // Load each distinct Q/K/V vector exactly once (half4 -> float4)
    float4 q[4], k[4], v[4];
    #pragma unroll
    for (int m = 0; m < 4; ++m) {
        if (valid[m]) {
            __half2 a0 = *(const __half2*)(Q + off[m]);
            __half2 a1 = *(const __half2*)(Q + off[m] + 2);
            float2 fa = __half22float2(a0), fb = __half22float2(a1);
            q[m] = make_float4(fa.x, fa.y, fb.x, fb.y);
            a0 = *(const __half2*)(K + off[m]);
            a1 = *(const __half2*)(K + off[m] + 2);
            fa = __half22float2(a0); fb = __half22float2(a1);
            k[m] = make_float4(fa.x, fa.y, fb.x, fb.y);
            a0 = *(const __half2*)(V + off[m]);
            a1 = *(const __half2*)(V + off[m] + 2);
            fa = __half22float2(a0); fb = __half22float2(a1);
            v[m] = make_float4(fa.x, fa.y, fb.x, fb.y);
        } else {
            q[m] = make_float4(0.f, 0.f, 0.f, 0.f);
            k[m] = q[m];
            v[m] = q[m];
        }
    }

    // 12 partial dots, then butterfly-reduce within each 16-lane head group
    float d[4][3];
    #pragma unroll
    for (int m = 0; m < 4; ++m)
        #pragma unroll
        for (int jj = 0; jj < 3; ++jj) {
            const float4 kk = k[routes[m][jj]];
            d[m][jj] = q[m].x*kk.x + q[m].y*kk.y + q[m].z*kk.z + q[m].w*kk.w;
        }
    #pragma unroll
    for (int offs = 8; offs > 0; offs >>= 1)
        #pragma unroll
        for (int m = 0; m < 4; ++m)
            #pragma unroll
            for (int jj = 0; jj < 3; ++jj)
                d[m][jj] += __shfl_xor_sync(0xffffffffu, d[m][jj], offs);

    // Softmax per m + weighted V accumulation
    float4 acc = make_float4(0.f, 0.f, 0.f, 0.f);
    #pragma unroll
    for (int m = 0; m < 4; ++m) {
        float sc0 = d[m][0] * scale;
        float sc1 = d[m][1] * scale;
        float sc2 = d[m][2] * scale;
        float mx = fmaxf(sc0, fmaxf(sc1, sc2));
        float e0 = expf(sc0 - mx);
        float e1 = expf(sc1 - mx);
        float e2 = expf(sc2 - mx);
        float inv = 1.0f / (e0 + e1 + e2);
        float a0 = e0 * inv, a1 = e1 * inv, a2 = e2 * inv;
        const float4 v0 = v[routes[m][0]];
        const float4 v1 = v[routes[m][1]];
        const float4 v2 = v[routes[m][2]];
        acc.x += a0 * v0.x + a1 * v1.x + a2 * v2.x;
        acc.y += a0 * v0.y + a1 * v1.y + a2 * v2.y;
        acc.z += a0 * v0.z + a1 * v1.z + a2 * v2.z;
        acc.w += a0 * v0.w + a1 * v1.w + a2 * v2.w;
    }

    long o = ((long)b * Ss + s) * Dd + lo;
    __half2 p0 = __floats2half2_rn(acc.x * 0.25f, acc.y * 0.25f);
    __half2 p1 = __floats2half2_rn(acc.z * 0.25f, acc.w * 0.25f);
    uint2 pk;
    pk.x = *(unsigned*)&p0;
    pk.y = *(unsigned*)&p1;
    *(uint2*)(f1 + o) = pk;
}

// ---------------------------------------------------------------------------
extern "C" void kernel_launch(void* const* d_in, const int* in_sizes, int n_in,
                              void* d_out, int out_size)
{
    const float *x[4], *Wm[4], *bm[4];
    const float *mod_emb, *Wq, *bq, *Wk, *bk, *Wv, *bv, *Wo, *bo, *temp;

    if (in_sizes[1] == 786432) {
        x[0]  = (const float*)d_in[0];  Wm[0] = (const float*)d_in[1];  bm[0] = (const float*)d_in[2];
        x[1]  = (const float*)d_in[3];  Wm[1] = (const float*)d_in[4];  bm[1] = (const float*)d_in[5];
        x[2]  = (const float*)d_in[6];  Wm[2] = (const float*)d_in[7];  bm[2] = (const float*)d_in[8];
        x[3]  = (const float*)d_in[9];  Wm[3] = (const float*)d_in[10]; bm[3] = (const float*)d_in[11];
    } else {
        x[0]  = (const float*)d_in[0];  x[1]  = (const float*)d_in[1];
        x[2]  = (const float*)d_in[2];  x[3]  = (const float*)d_in[3];
        Wm[0] = (const float*)d_in[4];  bm[0] = (const float*)d_in[5];
        Wm[1] = (const float*)d_in[6];  bm[1] = (const float*)d_in[7];
        Wm[2] = (const float*)d_in[8];  bm[2] = (const float*)d_in[9];
        Wm[3] = (const float*)d_in[10]; bm[3] = (const float*)d_in[11];
    }
    mod_emb = (const float*)d_in[12];
    Wq = (const float*)d_in[13]; bq = (const float*)d_in[14];
    Wk = (const float*)d_in[15]; bk = (const float*)d_in[16];
    Wv = (const float*)d_in[17]; bv = (const float*)d_in[18];
    Wo = (const float*)d_in[19]; bo = (const float*)d_in[20];
    temp = (const float*)d_in[21];

    __half *xs1, *ws1, *ws2, *sb1, *fb1, *Qh, *Kh, *Vh;
    cudaGetSymbolAddress((void**)&xs1, g_xs1);
    cudaGetSymbolAddress((void**)&ws1, g_ws1);
    cudaGetSymbolAddress((void**)&ws2, g_ws2);
    cudaGetSymbolAddress((void**)&sb1, g_sb1);
    cudaGetSymbolAddress((void**)&Qh,  g_Qh);
    cudaGetSymbolAddress((void**)&Kh,  g_Kh);
    cudaGetSymbolAddress((void**)&Vh,  g_Vh);
    cudaGetSymbolAddress((void**)&fb1, g_fb1);

    // Persistent function attributes; set once outside graph capture.
    static bool attrSet = false;
    if (!attrSet) {
        cudaFuncSetAttribute(gemm_one,  cudaFuncAttributeMaxDynamicSharedMemorySize, 2 * 3 * ARR64);
        cudaFuncSetAttribute(gemm_qk,   cudaFuncAttributeMaxDynamicSharedMemorySize, 3 * 2 * ARR64);
        cudaFuncSetAttribute(gemm_v,    cudaFuncAttributeMaxDynamicSharedMemorySize, 2 * 3 * ARR64);
        cudaFuncSetAttribute(gemm_proj, cudaFuncAttributeMaxDynamicSharedMemorySize, 3 * 2 * ARR64);
        attrSet = true;
    }

    const int sls[4] = {2048, 1024, 1500, 512};
    const int kds[4] = {768, 1024, 512, 2048};
    const size_t xoff[4] = {0, 6291456, 10485760, 13631488};
    const size_t woff[4] = {0, 786432, 1835008, 2359296};
    const size_t wqkvo[4] = {4456448, 5505024, 6553600, 7602176};
    const long moff[4] = {0, 8192, 12288, 18288};
    const int blkStart[4] = {0, 64, 96, 143};   // cumulative 128-row blocks

    // 1) ALL converts/splits in one launch (1024 float4 per block):
    //    jobs 0-3: x -> fp16 hi;  4-7: Wm -> fp16 hi;  8-11: Wq/k/v/o -> hi+lo
    {
        ConvJobs cj;
        int blocks = 0;
        const float* wsrc[4] = {Wq, Wk, Wv, Wo};
        for (int m = 0; m < 4; ++m) {
            int n4 = (int)(((size_t)Bb * sls[m] * kds[m]) / 4);
            cj.src[m] = (const float4*)x[m];
            cj.d1[m]  = (__half2*)(xs1 + xoff[m]);
            cj.d2[m]  = nullptr;
            cj.start[m] = blocks;
            blocks += n4 / 1024;
        }
        for (int m = 0; m < 4; ++m) {
            int n4 = (int)(((size_t)1024 * kds[m]) / 4);
            cj.src[4 + m] = (const float4*)Wm[m];
            cj.d1[4 + m]  = (__half2*)(ws1 + woff[m]);
            cj.d2[4 + m]  = nullptr;
            cj.start[4 + m] = blocks;
            blocks += n4 / 1024;
        }
        for (int i = 0; i < 4; ++i) {
            cj.src[8 + i] = (const float4*)wsrc[i];
            cj.d1[8 + i]  = (__half2*)(ws1 + wqkvo[i]);
            cj.d2[8 + i]  = (__half2*)(ws2 + wqkvo[i]);
            cj.start[8 + i] = blocks;
            blocks += (1048576 / 4) / 1024;
        }
        cj.start[12] = blocks;
        conv_all<<<blocks, 256>>>(cj);
    }

    // 2) modality projections, ONE launch, 1-term, 3-stage BK=64
    {
        Jobs4 jobs;
        for (int m = 0; m < 4; ++m) {
            jobs.j[m].A1   = xs1 + xoff[m];
            jobs.j[m].W1   = ws1 + woff[m];
            jobs.j[m].bias = bm[m];
            jobs.j[m].extra = mod_emb + m * Dd;
            jobs.j[m].o1   = sb1 + moff[m] * Dd;
            jobs.j[m].R    = Bb * sls[m];
            jobs.j[m].Kd   = kds[m];
            jobs.j[m].blkStart = blkStart[m];
        }
        dim3 grid(8, 159);
        gemm_proj<<<grid, 256, 3 * 2 * ARR64>>>(jobs);
    }

    // 3a) Q+K projection: 1-term, 3-stage BK=64, homogeneous launch (fp16 out)
    {
        dim3 grid(16, (RTOT + 127) / 128);
        gemm_qk<<<grid, 256, 3 * 2 * ARR64>>>(sb1, ws1 + wqkvo[0],
                                              bq, bk, Qh, Kh, RTOT);
    }
    // 3b) V projection: 2-term, 2-stage BK=64 (fp16 out)
    {
        dim3 grid(8, (RTOT + 127) / 128);
        gemm_v<<<grid, 256, 2 * 3 * ARR64>>>(sb1, ws1 + wqkvo[0], ws2 + wqkvo[0],
                                             bv, Vh, RTOT);
    }

    // 4) routed attention + modality mean -> fp16 fused (2 heads/warp)
    attn_kernel<<<Bb * Ss, 256>>>(Qh, Kh, Vh, temp, fb1);

    // 5) output projection -> d_out (fp32, 2-term, 2-stage BK=64)
    {
        int R = Bb * Ss;   // 8192
        dim3 grid(8, R / 128);
        gemm_one<<<grid, 256, 2 * 3 * ARR64>>>(fb1, ws1 + wqkvo[3], ws2 + wqkvo[3],
                                               bo, (float*)d_out, R, Dd);
    }
}